// round 5
// baseline (speedup 1.0000x reference)
#include <cuda_runtime.h>
#include <math.h>

#define VOCAB 32000
#define D_IN  512
#define D_H   1024
#define D3H   3072
#define D_OUT 64
#define BB    64
#define SS    256
#define NCTA  128

typedef unsigned long long u64t;

// ---------------- scratch (static device globals; zero-init at load) ----------
// gi transposed: [3H rows][S*B cols]  (row = gate*1024+j, col = s*64+b)
__device__ float g_gi[(size_t)D3H * SS * BB];
// h transposed: [s][j][b]
__device__ float g_hs[(size_t)SS * D_H * BB];
__device__ float g_h0[D_H * BB];                // all-zero h(-1), never written

// ---------------- grid barrier state (R3 proven protocol) ----------------------
__device__ unsigned g_cnt = 0;
__device__ volatile unsigned g_flag = 0;        // cumulative barriers passed (monotonic)

// ---------------- f32x2 helpers ------------------------------------------------
__device__ __forceinline__ void fma2(u64t& c, u64t a, u64t b) {
    asm("fma.rn.f32x2 %0, %1, %2, %0;" : "+l"(c) : "l"(a), "l"(b));
}
__device__ __forceinline__ float2 up2(u64t v) {
    float2 r;
    asm("mov.b64 {%0, %1}, %2;" : "=f"(r.x), "=f"(r.y) : "l"(v));
    return r;
}
__device__ __forceinline__ u64t dup64(float w) {
    u64t r;
    asm("mov.b64 %0, {%1, %1};" : "=l"(r) : "f"(w));
    return r;
}

// ==============================================================================
// Kernel 1: g_gi[n][m] = sum_d w_ih[n][d] * emb[x(m)][d] + b_ih[n]   (unchanged)
// ==============================================================================
__global__ __launch_bounds__(256) void gi_gemm(
    const int* __restrict__ x, const float* __restrict__ emb,
    const float* __restrict__ w_ih, const float* __restrict__ b_ih)
{
    __shared__ float2 As2[16][128];   // 16 KB (w_ih side, duplicated)
    __shared__ float  Bs [16][128];   //  8 KB (gathered emb side)

    const int tid   = threadIdx.x;
    const int m_blk = blockIdx.y * 128;    // w_ih rows
    const int n_blk = blockIdx.x * 128;    // token cols

    const float* aptr[2]; int arow[2], akq[2];
    const float* bptr[2];
#pragma unroll
    for (int t = 0; t < 2; t++) {
        int i   = tid + t * 256;            // 0..511
        arow[t] = i >> 2;                   // 0..127
        akq[t]  = (i & 3) * 4;
        aptr[t] = w_ih + (size_t)(m_blk + arow[t]) * D_IN;
        int n = n_blk + arow[t];
        int s = n >> 6, b = n & 63;         // n = s*B + b
        int tok = x[b * SS + s];
        bptr[t] = emb + (size_t)tok * D_IN;
    }

    u64t c2[8][4];
#pragma unroll
    for (int i = 0; i < 8; i++)
#pragma unroll
        for (int j = 0; j < 4; j++) c2[i][j] = 0ull;

    const int ty = tid >> 4, tx = tid & 15;

    for (int kt = 0; kt < D_IN; kt += 16) {
#pragma unroll
        for (int t = 0; t < 2; t++) {
            float4 v = *(const float4*)(aptr[t] + kt + akq[t]);
            As2[akq[t]+0][arow[t]] = make_float2(v.x, v.x);
            As2[akq[t]+1][arow[t]] = make_float2(v.y, v.y);
            As2[akq[t]+2][arow[t]] = make_float2(v.z, v.z);
            As2[akq[t]+3][arow[t]] = make_float2(v.w, v.w);
            float4 w = *(const float4*)(bptr[t] + kt + akq[t]);
            Bs[akq[t]+0][arow[t]] = w.x;
            Bs[akq[t]+1][arow[t]] = w.y;
            Bs[akq[t]+2][arow[t]] = w.z;
            Bs[akq[t]+3][arow[t]] = w.w;
        }
        __syncthreads();
#pragma unroll
        for (int k = 0; k < 16; k++) {
            u64t ad[8], bb[4];
#pragma unroll
            for (int i = 0; i < 4; i++) {
                ad[i]     = *(const u64t*)&As2[k][ty*4 + i];
                ad[i + 4] = *(const u64t*)&As2[k][64 + ty*4 + i];
            }
            bb[0] = *(const u64t*)&Bs[k][tx*4];
            bb[1] = *(const u64t*)&Bs[k][tx*4 + 2];
            bb[2] = *(const u64t*)&Bs[k][64 + tx*4];
            bb[3] = *(const u64t*)&Bs[k][64 + tx*4 + 2];
#pragma unroll
            for (int i = 0; i < 8; i++)
#pragma unroll
                for (int j = 0; j < 4; j++)
                    fma2(c2[i][j], ad[i], bb[j]);
        }
        __syncthreads();
    }

#pragma unroll
    for (int i = 0; i < 8; i++) {
        int mi = (i < 4) ? (ty*4 + i) : (64 + ty*4 + (i - 4));
        size_t m = (size_t)(m_blk + mi);
        float bih = b_ih[m];
#pragma unroll
        for (int j = 0; j < 4; j++) {
            int nj = (j < 2) ? (tx*4 + j*2) : (64 + tx*4 + (j - 2)*2);
            int n  = n_blk + nj;
            float2 v = up2(c2[i][j]);
            v.x += bih;
            v.y += bih;
            *(float2*)(g_gi + m * (SS * BB) + n) = v;
        }
    }
}

// ==============================================================================
// Kernel 2: PERSISTENT GRU. 128 CTAs x 256 threads, 1 CTA/SM.
// Permuted dup layout (conflict-free A loads) + padded splitK scratch,
// with the R3-proven g_flag grid barrier.
// ==============================================================================
#define REDSTRIDE 68

__global__ void __launch_bounds__(256, 1) gru_persistent(
    const float* __restrict__ w_hh, const float* __restrict__ b_hh)
{
    extern __shared__ float smem[];
    float* ws   = smem;                       // [1024][24]        96 KB
    float* buf0 = smem + 24576;               // [128][128] dup    64 KB
    float* buf1 = smem + 24576 + 16384;       // [128][128] dup    64 KB
    float* red  = buf0;                       // [96][68]          26 KB (aliases buf0)
    u64t* ws8 = (u64t*)ws;

    const int tid  = threadIdx.x;
    const int j0   = blockIdx.x * 8;
    const int wid  = tid >> 5;
    const int lane = tid & 31;
    // permuted dup-store float offset within a 128-float dup row:
    // even lane L=2d holds b-pair (4d,4d+1)   -> floats 4d..4d+3   (first half)
    // odd  lane L=2d+1 holds (4d+2,4d+3)      -> floats 64+4d..    (second half)
    const int dupoff = (lane & 1) ? (64 + (lane >> 1) * 4) : ((lane >> 1) * 4);

    // ---- preload weight slice: ws[k][g*8+jj] = w_hh[g*1024 + j0+jj][k]
    for (int idx = tid; idx < 24 * 256; idx += 256) {
        int r = idx >> 8;            // 0..23
        int q = idx & 255;           // k quad
        int g = r >> 3, jj = r & 7;
        float4 v = *(const float4*)(w_hh + (size_t)(g * D_H + j0 + jj) * D_H + q * 4);
        ws[(q*4+0)*24 + r] = v.x;
        ws[(q*4+1)*24 + r] = v.y;
        ws[(q*4+2)*24 + r] = v.z;
        ws[(q*4+3)*24 + r] = v.w;
    }

    unsigned base = 0;
    if (tid == 0) base = g_flag;    // safe: flag can't advance until all CTAs arrive
    __syncthreads();

    const int g4  = tid >> 6;       // splitK group 0..3 (uniform per warp-pair)
    const int pos = tid & 63;
    const int bg  = pos >> 2;       // 0..15 (4 b's each)
    const int jp  = pos & 3;        // j-pair 0..3

    for (int s = 0; s < SS; s++) {
        const float* hp = (s == 0) ? g_h0 : (g_hs + (size_t)(s - 1) * D_H * BB);

        // ---- prefetch epilogue operands for this step ----
        float e_gir[2], e_giz[2], e_gin[2], e_hp[2];
        const float* gi0 = g_gi + (size_t)s * 64;
#pragma unroll
        for (int ii = 0; ii < 2; ii++) {
            int o  = tid + ii * 256;
            int jj = o >> 6, b = o & 63;
            int j  = j0 + jj;
            const float* gip = gi0 + (size_t)j * (SS * BB) + b;
            e_gir[ii] = gip[0];
            e_giz[ii] = gip[(size_t)D_H * SS * BB];
            e_gin[ii] = gip[(size_t)2 * D_H * SS * BB];
            e_hp[ii]  = hp[(size_t)j * 64 + b];
        }

        u64t acc[4][3];
#pragma unroll
        for (int u = 0; u < 4; u++)
#pragma unroll
            for (int g = 0; g < 3; g++) acc[u][g] = 0ull;

        // ---- stage tile 0 directly (permuted dup layout) ----
#pragma unroll
        for (int c = 0; c < 16; c++) {
            int row = wid * 16 + c;
            float2 v = *(const float2*)(hp + (size_t)row * 64 + lane * 2);
            *(float4*)(buf0 + row * 128 + dupoff) = make_float4(v.x, v.x, v.y, v.y);
        }
        __syncthreads();

        for (int t = 0; t < 8; t++) {
            // prefetch next tile into registers (hidden behind compute)
            u64t pf[16];
            if (t < 7) {
#pragma unroll
                for (int c = 0; c < 16; c++) {
                    int row = wid * 16 + c;
                    pf[c] = *(const u64t*)(hp + (size_t)((t + 1) * 128 + row) * 64 + lane * 2);
                }
            }

            // compute tile t.  Permuted layout:
            //   dup(4bg),dup(4bg+1)   at u64 idx kl*64 + bg*2        (floats 4bg..)
            //   dup(4bg+2),dup(4bg+3) at u64 idx kl*64 + 32 + bg*2   (floats 64+4bg..)
            const u64t* b8 = (const u64t*)((t & 1) ? buf1 : buf0);
            const int kw = (t * 128 + g4 * 32) * 12;    // ws8 base for this group
#pragma unroll 4
            for (int kk = 0; kk < 32; kk++) {
                int kl = g4 * 32 + kk;
                ulonglong2 A01 = *(const ulonglong2*)(b8 + kl*64 + bg*2);
                ulonglong2 A23 = *(const ulonglong2*)(b8 + kl*64 + 32 + bg*2);
                u64t w0 = ws8[kw + kk*12 + 0*4 + jp];
                u64t w1 = ws8[kw + kk*12 + 1*4 + jp];
                u64t w2 = ws8[kw + kk*12 + 2*4 + jp];
                fma2(acc[0][0], A01.x, w0); fma2(acc[1][0], A01.y, w0);
                fma2(acc[2][0], A23.x, w0); fma2(acc[3][0], A23.y, w0);
                fma2(acc[0][1], A01.x, w1); fma2(acc[1][1], A01.y, w1);
                fma2(acc[2][1], A23.x, w1); fma2(acc[3][1], A23.y, w1);
                fma2(acc[0][2], A01.x, w2); fma2(acc[1][2], A01.y, w2);
                fma2(acc[2][2], A23.x, w2); fma2(acc[3][2], A23.y, w2);
            }

            if (t < 7) {
                float* dst = (t & 1) ? buf0 : buf1;     // the buffer NOT being read
#pragma unroll
                for (int c = 0; c < 16; c++) {
                    int row = wid * 16 + c;
                    float2 v = up2(pf[c]);
                    *(float4*)(dst + row * 128 + dupoff) = make_float4(v.x, v.x, v.y, v.y);
                }
                __syncthreads();
            }
        }

        // ---- splitK partial sums -> red (stride 68, conflict-free) ----
#pragma unroll
        for (int u = 0; u < 4; u++) {
            int b = bg * 4 + u;
#pragma unroll
            for (int g = 0; g < 3; g++) {
                float2 p = up2(acc[u][g]);
                red[((g4*3 + g)*8 + jp*2 + 0)*REDSTRIDE + b] = p.x;
                red[((g4*3 + g)*8 + jp*2 + 1)*REDSTRIDE + b] = p.y;
            }
        }
        __syncthreads();

        // ---- gate epilogue: 512 outputs, 2 per thread, coalesced store ----
        float* hout = g_hs + (size_t)s * D_H * BB;
#pragma unroll
        for (int ii = 0; ii < 2; ii++) {
            int o  = tid + ii * 256;
            int jj = o >> 6, b = o & 63;
            int j  = j0 + jj;
            float ghr = 0.f, ghz = 0.f, ghn = 0.f;
#pragma unroll
            for (int g = 0; g < 4; g++) {
                ghr += red[((g*3 + 0)*8 + jj)*REDSTRIDE + b];
                ghz += red[((g*3 + 1)*8 + jj)*REDSTRIDE + b];
                ghn += red[((g*3 + 2)*8 + jj)*REDSTRIDE + b];
            }
            float r = 1.f / (1.f + expf(-(e_gir[ii] + ghr + b_hh[j])));
            float z = 1.f / (1.f + expf(-(e_giz[ii] + ghz + b_hh[D_H + j])));
            float n = tanhf(e_gin[ii] + r * (ghn + b_hh[2 * D_H + j]));
            hout[(size_t)j * 64 + b] = (1.f - z) * n + z * e_hp[ii];
        }

        // ---- grid barrier (R3 proven: count + monotonic flag release) ----
        __syncthreads();
        if (tid == 0) {
            __threadfence();
            unsigned target = base + (unsigned)(s + 1);
            unsigned old = atomicAdd(&g_cnt, 1u);
            if (old == NCTA - 1) {
                atomicExch(&g_cnt, 0u);
                __threadfence();
                atomicExch((unsigned*)&g_flag, target);
            } else {
                while (g_flag < target) { }
            }
            __threadfence();
        }
        __syncthreads();
    }
}

// ==============================================================================
// Kernel 3: fc + log_softmax (unchanged)
// ==============================================================================
__global__ __launch_bounds__(256) void fc_lsm(
    const float* __restrict__ fc_w, const float* __restrict__ fc_b,
    float* __restrict__ out)
{
    __shared__ float hst[32 * 64];     // [k][b] natural, 8 KB
    __shared__ float wst[64 * 36];     // [o][k] padded,  9 KB
    __shared__ float L  [64 * 65];     // logits, 16.25 KB

    const int tid = threadIdx.x;
    const int s   = blockIdx.x;
    const float* hs_s = g_hs + (size_t)s * D_H * BB;
    const int og = tid & 15, bg = tid >> 4;

    u64t acc[2][4];
#pragma unroll
    for (int u = 0; u < 2; u++)
#pragma unroll
        for (int v = 0; v < 4; v++) acc[u][v] = 0ull;
    u64t* hst8 = (u64t*)hst;

    for (int k0 = 0; k0 < D_H; k0 += 32) {
        __syncthreads();
#pragma unroll
        for (int i = 0; i < 2; i++) {
            int q = tid + i * 256;
            int kl = q >> 4, bq = q & 15;
            *(float4*)(hst + kl*64 + bq*4) =
                *(const float4*)(hs_s + (size_t)(k0 + kl) * 64 + bq * 4);
        }
#pragma unroll
        for (int i = 0; i < 2; i++) {
            int q = tid + i * 256;
            int o = q >> 3, kq = q & 7;
            *(float4*)(wst + o*36 + kq*4) =
                *(const float4*)(fc_w + (size_t)o * D_H + k0 + kq * 4);
        }
        __syncthreads();
#pragma unroll 4
        for (int kk = 0; kk < 32; kk++) {
            u64t h0 = hst8[kk*32 + bg*2 + 0];
            u64t h1 = hst8[kk*32 + bg*2 + 1];
#pragma unroll
            for (int v = 0; v < 4; v++) {
                u64t wd = dup64(wst[(og*4 + v)*36 + kk]);
                fma2(acc[0][v], h0, wd);
                fma2(acc[1][v], h1, wd);
            }
        }
    }

    __syncthreads();
#pragma unroll
    for (int u = 0; u < 2; u++) {
#pragma unroll
        for (int v = 0; v < 4; v++) {
            float2 p = up2(acc[u][v]);
            int o  = og * 4 + v;
            int b0 = bg * 4 + u * 2;
            float bias = fc_b[o];
            L[(b0 + 0)*65 + o] = p.x + bias;
            L[(b0 + 1)*65 + o] = p.y + bias;
        }
    }
    __syncthreads();

    const int w = tid >> 5, lane = tid & 31;
#pragma unroll
    for (int rr = 0; rr < 8; rr++) {
        int b = w * 8 + rr;
        float v0 = L[b*65 + lane], v1 = L[b*65 + 32 + lane];
        float mx = fmaxf(v0, v1);
#pragma unroll
        for (int o = 16; o > 0; o >>= 1) mx = fmaxf(mx, __shfl_xor_sync(0xffffffffu, mx, o));
        float se = expf(v0 - mx) + expf(v1 - mx);
#pragma unroll
        for (int o = 16; o > 0; o >>= 1) se += __shfl_xor_sync(0xffffffffu, se, o);
        float lse = logf(se) + mx;
        float* op = out + ((size_t)b * SS + s) * D_OUT;
        op[lane]      = v0 - lse;
        op[lane + 32] = v1 - lse;
    }
}

// ==============================================================================
extern "C" void kernel_launch(void* const* d_in, const int* in_sizes, int n_in,
                              void* d_out, int out_size)
{
    (void)in_sizes; (void)n_in; (void)out_size;
    const int*   x    = (const int*)  d_in[0];
    const float* emb  = (const float*)d_in[1];
    const float* w_ih = (const float*)d_in[2];
    const float* w_hh = (const float*)d_in[3];
    const float* b_ih = (const float*)d_in[4];
    const float* b_hh = (const float*)d_in[5];
    const float* fc_w = (const float*)d_in[6];
    const float* fc_b = (const float*)d_in[7];
    float* out = (float*)d_out;

    const int rec_smem = (24576 + 16384 + 16384) * 4;   // 224 KB
    cudaFuncSetAttribute(gru_persistent,
                         cudaFuncAttributeMaxDynamicSharedMemorySize, rec_smem);

    gi_gemm<<<dim3((SS * BB) / 128, D3H / 128), 256>>>(x, emb, w_ih, b_ih);
    gru_persistent<<<NCTA, 256, rec_smem>>>(w_hh, b_hh);
    fc_lsm<<<SS, 256>>>(fc_w, fc_b, out);
}

// round 6
// speedup vs baseline: 1.0682x; 1.0682x over previous
#include <cuda_runtime.h>
#include <math.h>

#define VOCAB 32000
#define D_IN  512
#define D_H   1024
#define D3H   3072
#define D_OUT 64
#define BB    64
#define SS    256
#define NCTA  128

typedef unsigned long long u64t;

// ---------------- scratch (static device globals; zero-init at load) ----------
// gi transposed: [3H rows][S*B cols]  (row = gate*1024+j, col = s*64+b)
__device__ float g_gi[(size_t)D3H * SS * BB];
// h transposed: [s][j][b]
__device__ float g_hs[(size_t)SS * D_H * BB];
__device__ float g_h0[D_H * BB];                // all-zero h(-1), never written

// ---------------- grid barrier state (R3 proven protocol) ----------------------
__device__ unsigned g_cnt = 0;
__device__ volatile unsigned g_flag = 0;        // cumulative barriers passed (monotonic)

// ---------------- f32x2 helpers ------------------------------------------------
__device__ __forceinline__ void fma2(u64t& c, u64t a, u64t b) {
    asm("fma.rn.f32x2 %0, %1, %2, %0;" : "+l"(c) : "l"(a), "l"(b));
}
__device__ __forceinline__ float2 up2(u64t v) {
    float2 r;
    asm("mov.b64 {%0, %1}, %2;" : "=f"(r.x), "=f"(r.y) : "l"(v));
    return r;
}
__device__ __forceinline__ u64t dup64(float w) {
    u64t r;
    asm("mov.b64 %0, {%1, %1};" : "=l"(r) : "f"(w));
    return r;
}

// ==============================================================================
// Kernel 1: g_gi[n][m] = sum_d w_ih[n][d] * emb[x(m)][d] + b_ih[n]   (unchanged)
// ==============================================================================
__global__ __launch_bounds__(256) void gi_gemm(
    const int* __restrict__ x, const float* __restrict__ emb,
    const float* __restrict__ w_ih, const float* __restrict__ b_ih)
{
    __shared__ float2 As2[16][128];   // 16 KB (w_ih side, duplicated)
    __shared__ float  Bs [16][128];   //  8 KB (gathered emb side)

    const int tid   = threadIdx.x;
    const int m_blk = blockIdx.y * 128;    // w_ih rows
    const int n_blk = blockIdx.x * 128;    // token cols

    const float* aptr[2]; int arow[2], akq[2];
    const float* bptr[2];
#pragma unroll
    for (int t = 0; t < 2; t++) {
        int i   = tid + t * 256;            // 0..511
        arow[t] = i >> 2;                   // 0..127
        akq[t]  = (i & 3) * 4;
        aptr[t] = w_ih + (size_t)(m_blk + arow[t]) * D_IN;
        int n = n_blk + arow[t];
        int s = n >> 6, b = n & 63;         // n = s*B + b
        int tok = x[b * SS + s];
        bptr[t] = emb + (size_t)tok * D_IN;
    }

    u64t c2[8][4];
#pragma unroll
    for (int i = 0; i < 8; i++)
#pragma unroll
        for (int j = 0; j < 4; j++) c2[i][j] = 0ull;

    const int ty = tid >> 4, tx = tid & 15;

    for (int kt = 0; kt < D_IN; kt += 16) {
#pragma unroll
        for (int t = 0; t < 2; t++) {
            float4 v = *(const float4*)(aptr[t] + kt + akq[t]);
            As2[akq[t]+0][arow[t]] = make_float2(v.x, v.x);
            As2[akq[t]+1][arow[t]] = make_float2(v.y, v.y);
            As2[akq[t]+2][arow[t]] = make_float2(v.z, v.z);
            As2[akq[t]+3][arow[t]] = make_float2(v.w, v.w);
            float4 w = *(const float4*)(bptr[t] + kt + akq[t]);
            Bs[akq[t]+0][arow[t]] = w.x;
            Bs[akq[t]+1][arow[t]] = w.y;
            Bs[akq[t]+2][arow[t]] = w.z;
            Bs[akq[t]+3][arow[t]] = w.w;
        }
        __syncthreads();
#pragma unroll
        for (int k = 0; k < 16; k++) {
            u64t ad[8], bb[4];
#pragma unroll
            for (int i = 0; i < 4; i++) {
                ad[i]     = *(const u64t*)&As2[k][ty*4 + i];
                ad[i + 4] = *(const u64t*)&As2[k][64 + ty*4 + i];
            }
            bb[0] = *(const u64t*)&Bs[k][tx*4];
            bb[1] = *(const u64t*)&Bs[k][tx*4 + 2];
            bb[2] = *(const u64t*)&Bs[k][64 + tx*4];
            bb[3] = *(const u64t*)&Bs[k][64 + tx*4 + 2];
#pragma unroll
            for (int i = 0; i < 8; i++)
#pragma unroll
                for (int j = 0; j < 4; j++)
                    fma2(c2[i][j], ad[i], bb[j]);
        }
        __syncthreads();
    }

#pragma unroll
    for (int i = 0; i < 8; i++) {
        int mi = (i < 4) ? (ty*4 + i) : (64 + ty*4 + (i - 4));
        size_t m = (size_t)(m_blk + mi);
        float bih = b_ih[m];
#pragma unroll
        for (int j = 0; j < 4; j++) {
            int nj = (j < 2) ? (tx*4 + j*2) : (64 + tx*4 + (j - 2)*2);
            int n  = n_blk + nj;
            float2 v = up2(c2[i][j]);
            v.x += bih;
            v.y += bih;
            *(float2*)(g_gi + m * (SS * BB) + n) = v;
        }
    }
}

// ==============================================================================
// Kernel 2: PERSISTENT GRU. 128 CTAs x 256 threads, 1 CTA/SM.
// Fully conflict-free SMEM: A01/A23 reads 1 wf each (sigma-permuted dup rows),
// w loads split into ws01 (LDS.128) + ws2 (LDS.64), dup-store 4-wf optimal.
// R3-proven g_flag grid barrier.
// ==============================================================================
#define REDSTRIDE 68

__global__ void __launch_bounds__(256, 1) gru_persistent(
    const float* __restrict__ w_hh, const float* __restrict__ b_hh)
{
    extern __shared__ float smem[];
    float* ws01f = smem;                      // [1024][16]  (g0,g1 pairs) 64 KB
    float* ws2f  = smem + 16384;              // [1024][8]   (g2 pairs)    32 KB
    float* buf0  = smem + 24576;              // [128][128] dup            64 KB
    float* buf1  = smem + 24576 + 16384;      // [128][128] dup            64 KB
    float* red   = buf0;                      // [96][68]                  26 KB (aliases buf0)
    u64t* ws01 = (u64t*)ws01f;
    u64t* ws2  = (u64t*)ws2f;

    const int tid  = threadIdx.x;
    const int j0   = blockIdx.x * 8;
    const int wid  = tid >> 5;
    const int lane = tid & 31;
    // dup-store float offset within a 128-float dup row:
    // even lane 2d  -> b-pair (4d,4d+1)   at float 4d            (region 1)
    // odd  lane 2d+1-> b-pair (4d+2,4d+3) at float 64 + 4*sigma(d), sigma(d)=((d+4)&7)|(d&8)
    const int dhalf  = lane >> 1;
    const int sig_l  = ((dhalf + 4) & 7) | (dhalf & 8);
    const int dupoff = (lane & 1) ? (64 + 4 * sig_l) : (4 * dhalf);

    // ---- preload weight slice into split layout:
    //   ws01 u64[k*8 + jp*2 + g] = (w[g][j0+2jp], w[g][j0+2jp+1]) for g in {0,1}
    //   ws2  u64[k*4 + jp]       = (w[2][j0+2jp], w[2][j0+2jp+1])
    for (int idx = tid; idx < 24 * 256; idx += 256) {
        int r = idx >> 8;            // 0..23
        int q = idx & 255;           // k quad
        int g = r >> 3, jj = r & 7;
        int jp = jj >> 1, e = jj & 1;
        float4 v = *(const float4*)(w_hh + (size_t)(g * D_H + j0 + jj) * D_H + q * 4);
        if (g < 2) {
            int o = 4 * jp + 2 * g + e;
            ws01f[(q*4+0)*16 + o] = v.x;
            ws01f[(q*4+1)*16 + o] = v.y;
            ws01f[(q*4+2)*16 + o] = v.z;
            ws01f[(q*4+3)*16 + o] = v.w;
        } else {
            int o = 2 * jp + e;
            ws2f[(q*4+0)*8 + o] = v.x;
            ws2f[(q*4+1)*8 + o] = v.y;
            ws2f[(q*4+2)*8 + o] = v.z;
            ws2f[(q*4+3)*8 + o] = v.w;
        }
    }

    unsigned base = 0;
    if (tid == 0) base = g_flag;    // safe: flag can't advance until all CTAs arrive
    __syncthreads();

    const int g4  = tid >> 6;       // splitK group 0..3 (uniform per warp-pair)
    const int pos = tid & 63;
    const int bg  = pos >> 2;       // 0..15 (4 b's each)
    const int jp  = pos & 3;        // j-pair 0..3
    const int sbg = ((bg + 4) & 7) | (bg & 8);   // sigma(bg) for A23 reads

    for (int s = 0; s < SS; s++) {
        const float* hp = (s == 0) ? g_h0 : (g_hs + (size_t)(s - 1) * D_H * BB);

        // ---- prefetch epilogue operands for this step ----
        float e_gir[2], e_giz[2], e_gin[2], e_hp[2];
        const float* gi0 = g_gi + (size_t)s * 64;
#pragma unroll
        for (int ii = 0; ii < 2; ii++) {
            int o  = tid + ii * 256;
            int jj = o >> 6, b = o & 63;
            int j  = j0 + jj;
            const float* gip = gi0 + (size_t)j * (SS * BB) + b;
            e_gir[ii] = gip[0];
            e_giz[ii] = gip[(size_t)D_H * SS * BB];
            e_gin[ii] = gip[(size_t)2 * D_H * SS * BB];
            e_hp[ii]  = hp[(size_t)j * 64 + b];
        }

        u64t acc[4][3];
#pragma unroll
        for (int u = 0; u < 4; u++)
#pragma unroll
            for (int g = 0; g < 3; g++) acc[u][g] = 0ull;

        // ---- stage tile 0 directly (sigma-permuted dup layout) ----
#pragma unroll
        for (int c = 0; c < 16; c++) {
            int row = wid * 16 + c;
            float2 v = *(const float2*)(hp + (size_t)row * 64 + lane * 2);
            *(float4*)(buf0 + row * 128 + dupoff) = make_float4(v.x, v.x, v.y, v.y);
        }
        __syncthreads();

        for (int t = 0; t < 8; t++) {
            // prefetch next tile into registers (hidden behind compute)
            u64t pf[16];
            if (t < 7) {
#pragma unroll
                for (int c = 0; c < 16; c++) {
                    int row = wid * 16 + c;
                    pf[c] = *(const u64t*)(hp + (size_t)((t + 1) * 128 + row) * 64 + lane * 2);
                }
            }

            // compute tile t
            const u64t* b8 = (const u64t*)((t & 1) ? buf1 : buf0);
            const u64t* w01p = ws01 + (size_t)(t * 128 + g4 * 32) * 8 + jp * 2;
            const u64t* w2p  = ws2  + (size_t)(t * 128 + g4 * 32) * 4 + jp;
#pragma unroll 4
            for (int kk = 0; kk < 32; kk++) {
                int kl = g4 * 32 + kk;
                ulonglong2 A01 = *(const ulonglong2*)(b8 + kl*64 + bg*2);
                ulonglong2 A23 = *(const ulonglong2*)(b8 + kl*64 + 32 + sbg*2);
                ulonglong2 W01 = *(const ulonglong2*)(w01p + kk*8);
                u64t w2v = w2p[kk*4];
                fma2(acc[0][0], A01.x, W01.x); fma2(acc[1][0], A01.y, W01.x);
                fma2(acc[2][0], A23.x, W01.x); fma2(acc[3][0], A23.y, W01.x);
                fma2(acc[0][1], A01.x, W01.y); fma2(acc[1][1], A01.y, W01.y);
                fma2(acc[2][1], A23.x, W01.y); fma2(acc[3][1], A23.y, W01.y);
                fma2(acc[0][2], A01.x, w2v);   fma2(acc[1][2], A01.y, w2v);
                fma2(acc[2][2], A23.x, w2v);   fma2(acc[3][2], A23.y, w2v);
            }

            if (t < 7) {
                float* dst = (t & 1) ? buf0 : buf1;     // the buffer NOT being read
#pragma unroll
                for (int c = 0; c < 16; c++) {
                    int row = wid * 16 + c;
                    float2 v = up2(pf[c]);
                    *(float4*)(dst + row * 128 + dupoff) = make_float4(v.x, v.x, v.y, v.y);
                }
                __syncthreads();
            }
        }

        // ---- splitK partial sums -> red (stride 68, conflict-free) ----
        // acc[0..1] = b-pairs (4bg,4bg+1); acc[2..3] = (4bg+2,4bg+3)
#pragma unroll
        for (int u = 0; u < 4; u++) {
            int b = bg * 4 + u;
#pragma unroll
            for (int g = 0; g < 3; g++) {
                float2 p = up2(acc[u][g]);
                red[((g4*3 + g)*8 + jp*2 + 0)*REDSTRIDE + b] = p.x;
                red[((g4*3 + g)*8 + jp*2 + 1)*REDSTRIDE + b] = p.y;
            }
        }
        __syncthreads();

        // ---- gate epilogue: 512 outputs, 2 per thread, coalesced store ----
        float* hout = g_hs + (size_t)s * D_H * BB;
#pragma unroll
        for (int ii = 0; ii < 2; ii++) {
            int o  = tid + ii * 256;
            int jj = o >> 6, b = o & 63;
            int j  = j0 + jj;
            float ghr = 0.f, ghz = 0.f, ghn = 0.f;
#pragma unroll
            for (int g = 0; g < 4; g++) {
                ghr += red[((g*3 + 0)*8 + jj)*REDSTRIDE + b];
                ghz += red[((g*3 + 1)*8 + jj)*REDSTRIDE + b];
                ghn += red[((g*3 + 2)*8 + jj)*REDSTRIDE + b];
            }
            float r = 1.f / (1.f + expf(-(e_gir[ii] + ghr + b_hh[j])));
            float z = 1.f / (1.f + expf(-(e_giz[ii] + ghz + b_hh[D_H + j])));
            float n = tanhf(e_gin[ii] + r * (ghn + b_hh[2 * D_H + j]));
            hout[(size_t)j * 64 + b] = (1.f - z) * n + z * e_hp[ii];
        }

        // ---- grid barrier (R3 proven: count + monotonic flag release) ----
        __syncthreads();
        if (tid == 0) {
            __threadfence();
            unsigned target = base + (unsigned)(s + 1);
            unsigned old = atomicAdd(&g_cnt, 1u);
            if (old == NCTA - 1) {
                atomicExch(&g_cnt, 0u);
                __threadfence();
                atomicExch((unsigned*)&g_flag, target);
            } else {
                while (g_flag < target) { }
            }
            __threadfence();
        }
        __syncthreads();
    }
}

// ==============================================================================
// Kernel 3: fc + log_softmax (unchanged)
// ==============================================================================
__global__ __launch_bounds__(256) void fc_lsm(
    const float* __restrict__ fc_w, const float* __restrict__ fc_b,
    float* __restrict__ out)
{
    __shared__ float hst[32 * 64];     // [k][b] natural, 8 KB
    __shared__ float wst[64 * 36];     // [o][k] padded,  9 KB
    __shared__ float L  [64 * 65];     // logits, 16.25 KB

    const int tid = threadIdx.x;
    const int s   = blockIdx.x;
    const float* hs_s = g_hs + (size_t)s * D_H * BB;
    const int og = tid & 15, bg = tid >> 4;

    u64t acc[2][4];
#pragma unroll
    for (int u = 0; u < 2; u++)
#pragma unroll
        for (int v = 0; v < 4; v++) acc[u][v] = 0ull;
    u64t* hst8 = (u64t*)hst;

    for (int k0 = 0; k0 < D_H; k0 += 32) {
        __syncthreads();
#pragma unroll
        for (int i = 0; i < 2; i++) {
            int q = tid + i * 256;
            int kl = q >> 4, bq = q & 15;
            *(float4*)(hst + kl*64 + bq*4) =
                *(const float4*)(hs_s + (size_t)(k0 + kl) * 64 + bq * 4);
        }
#pragma unroll
        for (int i = 0; i < 2; i++) {
            int q = tid + i * 256;
            int o = q >> 3, kq = q & 7;
            *(float4*)(wst + o*36 + kq*4) =
                *(const float4*)(fc_w + (size_t)o * D_H + k0 + kq * 4);
        }
        __syncthreads();
#pragma unroll 4
        for (int kk = 0; kk < 32; kk++) {
            u64t h0 = hst8[kk*32 + bg*2 + 0];
            u64t h1 = hst8[kk*32 + bg*2 + 1];
#pragma unroll
            for (int v = 0; v < 4; v++) {
                u64t wd = dup64(wst[(og*4 + v)*36 + kk]);
                fma2(acc[0][v], h0, wd);
                fma2(acc[1][v], h1, wd);
            }
        }
    }

    __syncthreads();
#pragma unroll
    for (int u = 0; u < 2; u++) {
#pragma unroll
        for (int v = 0; v < 4; v++) {
            float2 p = up2(acc[u][v]);
            int o  = og * 4 + v;
            int b0 = bg * 4 + u * 2;
            float bias = fc_b[o];
            L[(b0 + 0)*65 + o] = p.x + bias;
            L[(b0 + 1)*65 + o] = p.y + bias;
        }
    }
    __syncthreads();

    const int w = tid >> 5, lane = tid & 31;
#pragma unroll
    for (int rr = 0; rr < 8; rr++) {
        int b = w * 8 + rr;
        float v0 = L[b*65 + lane], v1 = L[b*65 + 32 + lane];
        float mx = fmaxf(v0, v1);
#pragma unroll
        for (int o = 16; o > 0; o >>= 1) mx = fmaxf(mx, __shfl_xor_sync(0xffffffffu, mx, o));
        float se = expf(v0 - mx) + expf(v1 - mx);
#pragma unroll
        for (int o = 16; o > 0; o >>= 1) se += __shfl_xor_sync(0xffffffffu, se, o);
        float lse = logf(se) + mx;
        float* op = out + ((size_t)b * SS + s) * D_OUT;
        op[lane]      = v0 - lse;
        op[lane + 32] = v1 - lse;
    }
}

// ==============================================================================
extern "C" void kernel_launch(void* const* d_in, const int* in_sizes, int n_in,
                              void* d_out, int out_size)
{
    (void)in_sizes; (void)n_in; (void)out_size;
    const int*   x    = (const int*)  d_in[0];
    const float* emb  = (const float*)d_in[1];
    const float* w_ih = (const float*)d_in[2];
    const float* w_hh = (const float*)d_in[3];
    const float* b_ih = (const float*)d_in[4];
    const float* b_hh = (const float*)d_in[5];
    const float* fc_w = (const float*)d_in[6];
    const float* fc_b = (const float*)d_in[7];
    float* out = (float*)d_out;

    const int rec_smem = (24576 + 16384 + 16384) * 4;   // 224 KB
    cudaFuncSetAttribute(gru_persistent,
                         cudaFuncAttributeMaxDynamicSharedMemorySize, rec_smem);

    gi_gemm<<<dim3((SS * BB) / 128, D3H / 128), 256>>>(x, emb, w_ih, b_ih);
    gru_persistent<<<NCTA, 256, rec_smem>>>(w_hh, b_hh);
    fc_lsm<<<SS, 256>>>(fc_w, fc_b, out);
}